// round 16
// baseline (speedup 1.0000x reference)
#include <cuda_runtime.h>
#include <cuda_fp16.h>
#include <math.h>
#include <cstdint>

#define NMAX 100000
#define EMAX 1600000
#define D 64
#define KDIM 192
#define OUTC 64

typedef unsigned long long u64;

// ---- scratch ----
__device__ int    g_cnt[NMAX];          // zero-init; self-cleaned by scan
__device__ int    g_start[NMAX + 1];
__device__ int    g_slot[EMAX];         // per-edge slot within its row
__device__ int    g_adj[EMAX];
__device__ u64    g_desc[256];          // lookback descriptors; reset by scatter
__device__ uint2  g_feat16[(size_t)NMAX * 16];   // [N, 64] fp16
__device__ __half g_comb[(size_t)NMAX * KDIM];   // [N, 192] fp16 sum|max|min
__device__ __half g_whi[KDIM * OUTC];            // W hi split [192][64]
__device__ __half g_wlo[KDIM * OUTC];            // W lo split

// ---- prep: feature fp32->fp16 + degree histogram with slot claim ----

__global__ __launch_bounds__(256) void prep_kernel(const float* __restrict__ feat,
                                                   const int* __restrict__ row,
                                                   int total4, int E) {
    int i = blockIdx.x * blockDim.x + threadIdx.x;
    if (i < total4) {
        float4 v = *(const float4*)&feat[(size_t)i * 4];
        __half2 h0 = __floats2half2_rn(v.x, v.y);
        __half2 h1 = __floats2half2_rn(v.z, v.w);
        uint2 u;
        u.x = *(uint32_t*)&h0;
        u.y = *(uint32_t*)&h1;
        g_feat16[i] = u;
    }
    if (i < E) {
        g_slot[i] = atomicAdd(&g_cnt[row[i]], 1);   // ATOMG ~ REDG @ n_conc>=13
    }
}

// ---------------- W hi/lo split ----------------

__global__ __launch_bounds__(256) void wprep_kernel(const float* __restrict__ W) {
    int i = blockIdx.x * blockDim.x + threadIdx.x;
    if (i < KDIM * OUTC) {
        float w = W[i];
        __half hi = __float2half_rn(w);
        __half lo = __float2half_rn(w - __half2float(hi));
        g_whi[i] = hi;
        g_wlo[i] = lo;
    }
}

// ---------------- single-pass decoupled-lookback scan ----------------

#define SCAN_B 512

__global__ __launch_bounds__(SCAN_B) void scan_lookback_kernel(int n, int nb) {
    __shared__ int ws[16];
    __shared__ int s_off;
    int bid = blockIdx.x, tid = threadIdx.x;
    int lane = tid & 31, wid = tid >> 5;
    int i = bid * SCAN_B + tid;

    int v = (i < n) ? g_cnt[i] : 0;
    if (i < n) g_cnt[i] = 0;                    // self-clean for next call

    int x = v;
    #pragma unroll
    for (int o = 1; o < 32; o <<= 1) {
        int y = __shfl_up_sync(0xffffffffu, x, o);
        if (lane >= o) x += y;
    }
    if (lane == 31) ws[wid] = x;
    __syncthreads();
    if (wid == 0 && lane < 16) {
        int w = ws[lane];
        #pragma unroll
        for (int o = 1; o < 16; o <<= 1) {
            int y = __shfl_up_sync(0x0000ffffu, w, o);
            if (lane >= o) w += y;
        }
        ws[lane] = w;
    }
    __syncthreads();
    int incl = x + (wid > 0 ? ws[wid - 1] : 0);
    int agg = ws[15];

    if (tid == 0) {
        u64 d = ((u64)(bid == 0 ? 2u : 1u) << 32) | (unsigned)agg;
        *((volatile u64*)&g_desc[bid]) = d;
        __threadfence();
        if (bid == 0) s_off = 0;
    }

    if (bid > 0 && wid == 0) {
        int lookbase = bid - 1;
        int run = 0;
        while (true) {
            int idx = lookbase - lane;
            u64 d;
            bool ready;
            do {
                d = (idx >= 0) ? *((volatile u64*)&g_desc[idx]) : (2ull << 32);
                ready = (unsigned)(d >> 32) != 0u;
            } while (!__all_sync(0xffffffffu, ready));
            unsigned pm = __ballot_sync(0xffffffffu, (unsigned)(d >> 32) == 2u);
            int val = (int)(unsigned)(d & 0xffffffffu);
            if (pm) {
                int fp = __ffs(pm) - 1;
                int contrib = (lane <= fp) ? val : 0;
                #pragma unroll
                for (int o = 16; o > 0; o >>= 1)
                    contrib += __shfl_down_sync(0xffffffffu, contrib, o);
                if (lane == 0) {
                    s_off = run + contrib;
                    u64 dn = (2ull << 32) | (unsigned)(run + contrib + agg);
                    *((volatile u64*)&g_desc[bid]) = dn;
                    __threadfence();
                }
                break;
            } else {
                int contrib = val;
                #pragma unroll
                for (int o = 16; o > 0; o >>= 1)
                    contrib += __shfl_down_sync(0xffffffffu, contrib, o);
                contrib = __shfl_sync(0xffffffffu, contrib, 0);
                run += contrib;
                lookbase -= 32;
            }
        }
    }
    __syncthreads();
    int off = s_off;

    if (i < n) g_start[i] = incl - v + off;
    if (tid == 0 && bid == nb - 1) g_start[n] = off + agg;
}

// ---------------- scatter: atomic-free placement ----------------

__global__ __launch_bounds__(256) void scatter_kernel(const int* __restrict__ row,
                                                      const int* __restrict__ col, int E) {
    int i = blockIdx.x * blockDim.x + threadIdx.x;
    if (i < 256) g_desc[i] = 0ull;              // reset lookback for next call
    if (i < E) {
        int r = row[i];
        g_adj[g_start[r] + g_slot[i]] = col[i];
    }
}

// ---------------- aggregation: half-warp per node, fp16 in/out ----------------

__device__ __forceinline__ void acc16(float4& sm, __half2& mxa, __half2& mxb,
                                      __half2& mna, __half2& mnb, uint2 u) {
    __half2 h0 = *(__half2*)&u.x;
    __half2 h1 = *(__half2*)&u.y;
    mxa = __hmax2(mxa, h0);  mxb = __hmax2(mxb, h1);
    mna = __hmin2(mna, h0);  mnb = __hmin2(mnb, h1);
    float2 f0 = __half22float2(h0);
    float2 f1 = __half22float2(h1);
    sm.x += f0.x;  sm.y += f0.y;  sm.z += f1.x;  sm.w += f1.y;
}

__global__ __launch_bounds__(256) void aggregate_kernel(int n) {
    int gt   = blockIdx.x * blockDim.x + threadIdx.x;
    int node = gt >> 4;
    int lane = gt & 15;
    if (node >= n) return;

    int s = g_start[node];
    int e = g_start[node + 1];

    float4 sm = make_float4(0.f, 0.f, 0.f, 0.f);
    __half2 ninf2 = __float2half2_rn(-INFINITY);
    __half2 pinf2 = __float2half2_rn( INFINITY);
    __half2 mxa = ninf2, mxb = ninf2;
    __half2 mna = pinf2, mnb = pinf2;

    int j = s;
    for (; j + 4 <= e; j += 4) {
        int c0 = __ldg(&g_adj[j]);
        int c1 = __ldg(&g_adj[j + 1]);
        int c2 = __ldg(&g_adj[j + 2]);
        int c3 = __ldg(&g_adj[j + 3]);
        uint2 u0 = g_feat16[(size_t)c0 * 16 + lane];
        uint2 u1 = g_feat16[(size_t)c1 * 16 + lane];
        uint2 u2 = g_feat16[(size_t)c2 * 16 + lane];
        uint2 u3 = g_feat16[(size_t)c3 * 16 + lane];
        acc16(sm, mxa, mxb, mna, mnb, u0);
        acc16(sm, mxa, mxb, mna, mnb, u1);
        acc16(sm, mxa, mxb, mna, mnb, u2);
        acc16(sm, mxa, mxb, mna, mnb, u3);
    }
    for (; j < e; j++) {
        int c0 = __ldg(&g_adj[j]);
        uint2 u0 = g_feat16[(size_t)c0 * 16 + lane];
        acc16(sm, mxa, mxb, mna, mnb, u0);
    }

    if (e == s) {
        __half2 z = __float2half2_rn(0.f);
        mxa = z; mxb = z; mna = z; mnb = z;
    }

    __half2 s01 = __floats2half2_rn(sm.x, sm.y);
    __half2 s23 = __floats2half2_rn(sm.z, sm.w);
    uint2 sw, xw, nw;
    sw.x = *(uint32_t*)&s01;  sw.y = *(uint32_t*)&s23;
    xw.x = *(uint32_t*)&mxa;  xw.y = *(uint32_t*)&mxb;
    nw.x = *(uint32_t*)&mna;  nw.y = *(uint32_t*)&mnb;
    __half* cb = &g_comb[(size_t)node * KDIM];
    *(uint2*)&cb[        4 * lane] = sw;
    *(uint2*)&cb[ D  +   4 * lane] = xw;
    *(uint2*)&cb[2*D +   4 * lane] = nw;
}

// ---------------- MLP GEMM via mma.sync m16n8k16 (HMMA), fp32 accum ----------------

__device__ __forceinline__ float tanh_fast(float x) {
    float y; asm("tanh.approx.f32 %0, %1;" : "=f"(y) : "f"(x)); return y;
}
__device__ __forceinline__ uint32_t smem_u32(const void* p) {
    uint32_t a;
    asm("{ .reg .u64 t; cvta.to.shared.u64 t, %1; cvt.u32.u64 %0, t; }" : "=r"(a) : "l"(p));
    return a;
}

#define GBM 128
#define SA_STR 200
#define SW_STR 72
#define SM_A 0
#define SM_WHI (GBM * SA_STR)
#define SM_WLO (SM_WHI + KDIM * SW_STR)
#define GEMM_SMEM_HALFS (SM_WLO + KDIM * SW_STR)
#define GEMM_SMEM_BYTES (GEMM_SMEM_HALFS * 2)

__global__ __launch_bounds__(256) void mlp_gemm_kernel(
    const float* __restrict__ bg, float* __restrict__ out, int n)
{
    extern __shared__ __half smh[];
    int tid = threadIdx.x;
    int block_m = blockIdx.x * GBM;

    #pragma unroll
    for (int i = 0; i < 12; i++) {
        int c = tid + 256 * i;
        int r = c / 24, c8 = c % 24;
        int gm = block_m + r;
        uint4 v = make_uint4(0u, 0u, 0u, 0u);
        if (gm < n) v = *(const uint4*)&g_comb[(size_t)gm * KDIM + c8 * 8];
        *(uint4*)&smh[SM_A + r * SA_STR + c8 * 8] = v;
    }
    #pragma unroll
    for (int i = 0; i < 6; i++) {
        int c = tid + 256 * i;
        int r = c / 8, c8 = c % 8;
        *(uint4*)&smh[SM_WHI + r * SW_STR + c8 * 8] = *(const uint4*)&g_whi[r * OUTC + c8 * 8];
        *(uint4*)&smh[SM_WLO + r * SW_STR + c8 * 8] = *(const uint4*)&g_wlo[r * OUTC + c8 * 8];
    }
    __syncthreads();

    int lane = tid & 31;
    int wid = tid >> 5;
    int warp_m = wid >> 1;
    int warp_n = wid & 1;

    float acc[2][4][4];
    #pragma unroll
    for (int mt = 0; mt < 2; mt++)
        #pragma unroll
        for (int nt = 0; nt < 4; nt++)
            #pragma unroll
            for (int q = 0; q < 4; q++) acc[mt][nt][q] = 0.f;

    int a_row = warp_m * 32 + (lane & 15);
    int a_koff = (lane >> 4) * 8;
    int b_krow = (lane & 7) + ((lane >> 3) & 1) * 8;
    uint32_t sA = smem_u32(smh);

    #pragma unroll
    for (int ks = 0; ks < 12; ks++) {
        int k0 = ks * 16;
        uint32_t a[2][4];
        #pragma unroll
        for (int mt = 0; mt < 2; mt++) {
            uint32_t addr = sA + 2 * ((a_row + mt * 16) * SA_STR + k0 + a_koff);
            asm volatile("ldmatrix.sync.aligned.m8n8.x4.shared.b16 {%0,%1,%2,%3}, [%4];"
                : "=r"(a[mt][0]), "=r"(a[mt][1]), "=r"(a[mt][2]), "=r"(a[mt][3]) : "r"(addr));
        }
        #pragma unroll
        for (int nt = 0; nt < 4; nt++) {
            int colb = warp_n * 32 + nt * 8;
            uint32_t addr_h = sA + 2 * (SM_WHI + (k0 + b_krow) * SW_STR + colb);
            uint32_t addr_l = sA + 2 * (SM_WLO + (k0 + b_krow) * SW_STR + colb);
            uint32_t bh0, bh1, bl0, bl1;
            asm volatile("ldmatrix.sync.aligned.m8n8.x2.trans.shared.b16 {%0,%1}, [%2];"
                : "=r"(bh0), "=r"(bh1) : "r"(addr_h));
            asm volatile("ldmatrix.sync.aligned.m8n8.x2.trans.shared.b16 {%0,%1}, [%2];"
                : "=r"(bl0), "=r"(bl1) : "r"(addr_l));
            #pragma unroll
            for (int mt = 0; mt < 2; mt++) {
                asm volatile(
                    "mma.sync.aligned.m16n8k16.row.col.f32.f16.f16.f32 "
                    "{%0,%1,%2,%3}, {%4,%5,%6,%7}, {%8,%9}, {%0,%1,%2,%3};"
                    : "+f"(acc[mt][nt][0]), "+f"(acc[mt][nt][1]),
                      "+f"(acc[mt][nt][2]), "+f"(acc[mt][nt][3])
                    : "r"(a[mt][0]), "r"(a[mt][1]), "r"(a[mt][2]), "r"(a[mt][3]),
                      "r"(bh0), "r"(bh1));
                asm volatile(
                    "mma.sync.aligned.m16n8k16.row.col.f32.f16.f16.f32 "
                    "{%0,%1,%2,%3}, {%4,%5,%6,%7}, {%8,%9}, {%0,%1,%2,%3};"
                    : "+f"(acc[mt][nt][0]), "+f"(acc[mt][nt][1]),
                      "+f"(acc[mt][nt][2]), "+f"(acc[mt][nt][3])
                    : "r"(a[mt][0]), "r"(a[mt][1]), "r"(a[mt][2]), "r"(a[mt][3]),
                      "r"(bl0), "r"(bl1));
            }
        }
    }

    int gid = lane >> 2, tig = lane & 3;
    #pragma unroll
    for (int mt = 0; mt < 2; mt++) {
        #pragma unroll
        for (int nt = 0; nt < 4; nt++) {
            int cbase = warp_n * 32 + nt * 8 + 2 * tig;
            float bx = bg[cbase], by = bg[cbase + 1];
            int r0 = block_m + warp_m * 32 + mt * 16 + gid;
            if (r0 < n) {
                float2 o;
                o.x = tanh_fast(acc[mt][nt][0] + bx);
                o.y = tanh_fast(acc[mt][nt][1] + by);
                *(float2*)&out[(size_t)r0 * OUTC + cbase] = o;
            }
            int r1 = r0 + 8;
            if (r1 < n) {
                float2 o;
                o.x = tanh_fast(acc[mt][nt][2] + bx);
                o.y = tanh_fast(acc[mt][nt][3] + by);
                *(float2*)&out[(size_t)r1 * OUTC + cbase] = o;
            }
        }
    }
}

// ---------------- launch ----------------

extern "C" void kernel_launch(void* const* d_in, const int* in_sizes, int n_in,
                              void* d_out, int out_size) {
    const int*   row  = (const int*)d_in[0];
    const int*   col  = (const int*)d_in[1];
    const float* feat = (const float*)d_in[2];
    const float* W    = (const float*)d_in[3];
    const float* b    = (const float*)d_in[4];
    float* out = (float*)d_out;

    int E = in_sizes[0];
    int N = in_sizes[2] / D;
    int nb = (N + SCAN_B - 1) / SCAN_B;
    int total4 = N * D / 4;
    int prep_n = (total4 > E) ? total4 : E;

    cudaFuncSetAttribute(mlp_gemm_kernel,
                         cudaFuncAttributeMaxDynamicSharedMemorySize, GEMM_SMEM_BYTES);

    prep_kernel<<<(prep_n + 255) / 256, 256>>>(feat, row, total4, E);
    wprep_kernel<<<(KDIM * OUTC + 255) / 256, 256>>>(W);
    scan_lookback_kernel<<<nb, SCAN_B>>>(N, nb);
    scatter_kernel<<<(E + 255) / 256, 256>>>(row, col, E);
    aggregate_kernel<<<(N * 16 + 255) / 256, 256>>>(N);
    mlp_gemm_kernel<<<(N + GBM - 1) / GBM, 256, GEMM_SMEM_BYTES>>>(b, out, N);
}

// round 17
// speedup vs baseline: 1.0954x; 1.0954x over previous
#include <cuda_runtime.h>
#include <cuda_fp16.h>
#include <math.h>
#include <cstdint>

#define NMAX 100000
#define EMAX 1600000
#define D 64
#define KDIM 192
#define OUTC 64

typedef unsigned long long u64;

// ---- scratch ----
__device__ int    g_cnt[NMAX];          // zero-init; self-cleaned by scan
__device__ int    g_start[NMAX + 1];
__device__ int    g_slot[EMAX];         // per-edge slot within its row
__device__ int    g_adj[EMAX];
__device__ u64    g_desc[256];          // lookback descriptors; reset by scatter
__device__ uint2  g_feat16[(size_t)NMAX * 16];   // [N, 64] fp16
__device__ __half g_comb[(size_t)NMAX * KDIM];   // [N, 192] fp16 sum|max|min
__device__ __half g_w16[KDIM * OUTC];            // W fp16 [192][64]

// ---- prep: feature fp32->fp16 + W fp16 + histogram with slot claim ----

__global__ __launch_bounds__(256) void prep_kernel(const float* __restrict__ feat,
                                                   const int* __restrict__ row,
                                                   const float* __restrict__ W,
                                                   int total4, int E) {
    int i = blockIdx.x * blockDim.x + threadIdx.x;
    if (i < total4) {
        float4 v = *(const float4*)&feat[(size_t)i * 4];
        __half2 h0 = __floats2half2_rn(v.x, v.y);
        __half2 h1 = __floats2half2_rn(v.z, v.w);
        uint2 u;
        u.x = *(uint32_t*)&h0;
        u.y = *(uint32_t*)&h1;
        g_feat16[i] = u;
    }
    if (i < KDIM * OUTC / 2) {
        float2 w = *(const float2*)&W[(size_t)i * 2];
        __half2 h = __floats2half2_rn(w.x, w.y);
        *(uint32_t*)&g_w16[i * 2] = *(uint32_t*)&h;
    }
    if (i < E) {
        g_slot[i] = atomicAdd(&g_cnt[row[i]], 1);
    }
}

// ---------------- single-pass decoupled-lookback scan ----------------

#define SCAN_B 512

__global__ __launch_bounds__(SCAN_B) void scan_lookback_kernel(int n, int nb) {
    __shared__ int ws[16];
    __shared__ int s_off;
    int bid = blockIdx.x, tid = threadIdx.x;
    int lane = tid & 31, wid = tid >> 5;
    int i = bid * SCAN_B + tid;

    int v = (i < n) ? g_cnt[i] : 0;
    if (i < n) g_cnt[i] = 0;                    // self-clean for next call

    int x = v;
    #pragma unroll
    for (int o = 1; o < 32; o <<= 1) {
        int y = __shfl_up_sync(0xffffffffu, x, o);
        if (lane >= o) x += y;
    }
    if (lane == 31) ws[wid] = x;
    __syncthreads();
    if (wid == 0 && lane < 16) {
        int w = ws[lane];
        #pragma unroll
        for (int o = 1; o < 16; o <<= 1) {
            int y = __shfl_up_sync(0x0000ffffu, w, o);
            if (lane >= o) w += y;
        }
        ws[lane] = w;
    }
    __syncthreads();
    int incl = x + (wid > 0 ? ws[wid - 1] : 0);
    int agg = ws[15];

    if (tid == 0) {
        u64 d = ((u64)(bid == 0 ? 2u : 1u) << 32) | (unsigned)agg;
        *((volatile u64*)&g_desc[bid]) = d;
        __threadfence();
        if (bid == 0) s_off = 0;
    }

    if (bid > 0 && wid == 0) {
        int lookbase = bid - 1;
        int run = 0;
        while (true) {
            int idx = lookbase - lane;
            u64 d;
            bool ready;
            do {
                d = (idx >= 0) ? *((volatile u64*)&g_desc[idx]) : (2ull << 32);
                ready = (unsigned)(d >> 32) != 0u;
            } while (!__all_sync(0xffffffffu, ready));
            unsigned pm = __ballot_sync(0xffffffffu, (unsigned)(d >> 32) == 2u);
            int val = (int)(unsigned)(d & 0xffffffffu);
            if (pm) {
                int fp = __ffs(pm) - 1;
                int contrib = (lane <= fp) ? val : 0;
                #pragma unroll
                for (int o = 16; o > 0; o >>= 1)
                    contrib += __shfl_down_sync(0xffffffffu, contrib, o);
                if (lane == 0) {
                    s_off = run + contrib;
                    u64 dn = (2ull << 32) | (unsigned)(run + contrib + agg);
                    *((volatile u64*)&g_desc[bid]) = dn;
                    __threadfence();
                }
                break;
            } else {
                int contrib = val;
                #pragma unroll
                for (int o = 16; o > 0; o >>= 1)
                    contrib += __shfl_down_sync(0xffffffffu, contrib, o);
                contrib = __shfl_sync(0xffffffffu, contrib, 0);
                run += contrib;
                lookbase -= 32;
            }
        }
    }
    __syncthreads();
    int off = s_off;

    if (i < n) g_start[i] = incl - v + off;
    if (tid == 0 && bid == nb - 1) g_start[n] = off + agg;
}

// ---------------- scatter: atomic-free placement ----------------

__global__ __launch_bounds__(256) void scatter_kernel(const int* __restrict__ row,
                                                      const int* __restrict__ col, int E) {
    int i = blockIdx.x * blockDim.x + threadIdx.x;
    if (i < 256) g_desc[i] = 0ull;              // reset lookback for next call
    if (i < E) {
        int r = row[i];
        g_adj[g_start[r] + g_slot[i]] = col[i];
    }
}

// ---------------- aggregation: half-warp per node, fp16 in/out ----------------

__device__ __forceinline__ void acc16(float4& sm, __half2& mxa, __half2& mxb,
                                      __half2& mna, __half2& mnb, uint2 u) {
    __half2 h0 = *(__half2*)&u.x;
    __half2 h1 = *(__half2*)&u.y;
    mxa = __hmax2(mxa, h0);  mxb = __hmax2(mxb, h1);
    mna = __hmin2(mna, h0);  mnb = __hmin2(mnb, h1);
    float2 f0 = __half22float2(h0);
    float2 f1 = __half22float2(h1);
    sm.x += f0.x;  sm.y += f0.y;  sm.z += f1.x;  sm.w += f1.y;
}

__global__ __launch_bounds__(256) void aggregate_kernel(int n) {
    int gt   = blockIdx.x * blockDim.x + threadIdx.x;
    int node = gt >> 4;
    int lane = gt & 15;
    if (node >= n) return;

    int s = g_start[node];
    int e = g_start[node + 1];

    float4 sm = make_float4(0.f, 0.f, 0.f, 0.f);
    __half2 ninf2 = __float2half2_rn(-INFINITY);
    __half2 pinf2 = __float2half2_rn( INFINITY);
    __half2 mxa = ninf2, mxb = ninf2;
    __half2 mna = pinf2, mnb = pinf2;

    int j = s;
    for (; j + 4 <= e; j += 4) {
        int c0 = __ldg(&g_adj[j]);
        int c1 = __ldg(&g_adj[j + 1]);
        int c2 = __ldg(&g_adj[j + 2]);
        int c3 = __ldg(&g_adj[j + 3]);
        uint2 u0 = g_feat16[(size_t)c0 * 16 + lane];
        uint2 u1 = g_feat16[(size_t)c1 * 16 + lane];
        uint2 u2 = g_feat16[(size_t)c2 * 16 + lane];
        uint2 u3 = g_feat16[(size_t)c3 * 16 + lane];
        acc16(sm, mxa, mxb, mna, mnb, u0);
        acc16(sm, mxa, mxb, mna, mnb, u1);
        acc16(sm, mxa, mxb, mna, mnb, u2);
        acc16(sm, mxa, mxb, mna, mnb, u3);
    }
    for (; j < e; j++) {
        int c0 = __ldg(&g_adj[j]);
        uint2 u0 = g_feat16[(size_t)c0 * 16 + lane];
        acc16(sm, mxa, mxb, mna, mnb, u0);
    }

    if (e == s) {
        __half2 z = __float2half2_rn(0.f);
        mxa = z; mxb = z; mna = z; mnb = z;
    }

    __half2 s01 = __floats2half2_rn(sm.x, sm.y);
    __half2 s23 = __floats2half2_rn(sm.z, sm.w);
    uint2 sw, xw, nw;
    sw.x = *(uint32_t*)&s01;  sw.y = *(uint32_t*)&s23;
    xw.x = *(uint32_t*)&mxa;  xw.y = *(uint32_t*)&mxb;
    nw.x = *(uint32_t*)&mna;  nw.y = *(uint32_t*)&mnb;
    __half* cb = &g_comb[(size_t)node * KDIM];
    *(uint2*)&cb[        4 * lane] = sw;
    *(uint2*)&cb[ D  +   4 * lane] = xw;
    *(uint2*)&cb[2*D +   4 * lane] = nw;
}

// ---------------- MLP GEMM via mma.sync m16n8k16 (HMMA), fp32 accum ----------------
// fp16 W (no lo-correction): output rel-err contribution ~1.4e-4.

__device__ __forceinline__ float tanh_fast(float x) {
    float y; asm("tanh.approx.f32 %0, %1;" : "=f"(y) : "f"(x)); return y;
}
__device__ __forceinline__ uint32_t smem_u32(const void* p) {
    uint32_t a;
    asm("{ .reg .u64 t; cvta.to.shared.u64 t, %1; cvt.u32.u64 %0, t; }" : "=r"(a) : "l"(p));
    return a;
}

#define GBM 128
#define SA_STR 200
#define SW_STR 72
#define SM_A 0
#define SM_W (GBM * SA_STR)
#define GEMM_SMEM_HALFS (SM_W + KDIM * SW_STR)
#define GEMM_SMEM_BYTES (GEMM_SMEM_HALFS * 2)

__global__ __launch_bounds__(256) void mlp_gemm_kernel(
    const float* __restrict__ bg, float* __restrict__ out, int n)
{
    extern __shared__ __half smh[];
    int tid = threadIdx.x;
    int block_m = blockIdx.x * GBM;

    #pragma unroll
    for (int i = 0; i < 12; i++) {
        int c = tid + 256 * i;
        int r = c / 24, c8 = c % 24;
        int gm = block_m + r;
        uint4 v = make_uint4(0u, 0u, 0u, 0u);
        if (gm < n) v = *(const uint4*)&g_comb[(size_t)gm * KDIM + c8 * 8];
        *(uint4*)&smh[SM_A + r * SA_STR + c8 * 8] = v;
    }
    #pragma unroll
    for (int i = 0; i < 6; i++) {
        int c = tid + 256 * i;
        int r = c / 8, c8 = c % 8;
        *(uint4*)&smh[SM_W + r * SW_STR + c8 * 8] = *(const uint4*)&g_w16[r * OUTC + c8 * 8];
    }
    __syncthreads();

    int lane = tid & 31;
    int wid = tid >> 5;
    int warp_m = wid >> 1;
    int warp_n = wid & 1;

    float acc[2][4][4];
    #pragma unroll
    for (int mt = 0; mt < 2; mt++)
        #pragma unroll
        for (int nt = 0; nt < 4; nt++)
            #pragma unroll
            for (int q = 0; q < 4; q++) acc[mt][nt][q] = 0.f;

    int a_row = warp_m * 32 + (lane & 15);
    int a_koff = (lane >> 4) * 8;
    int b_krow = (lane & 7) + ((lane >> 3) & 1) * 8;
    uint32_t sA = smem_u32(smh);

    #pragma unroll
    for (int ks = 0; ks < 12; ks++) {
        int k0 = ks * 16;
        uint32_t a[2][4];
        #pragma unroll
        for (int mt = 0; mt < 2; mt++) {
            uint32_t addr = sA + 2 * ((a_row + mt * 16) * SA_STR + k0 + a_koff);
            asm volatile("ldmatrix.sync.aligned.m8n8.x4.shared.b16 {%0,%1,%2,%3}, [%4];"
                : "=r"(a[mt][0]), "=r"(a[mt][1]), "=r"(a[mt][2]), "=r"(a[mt][3]) : "r"(addr));
        }
        #pragma unroll
        for (int nt = 0; nt < 4; nt++) {
            int colb = warp_n * 32 + nt * 8;
            uint32_t addr_w = sA + 2 * (SM_W + (k0 + b_krow) * SW_STR + colb);
            uint32_t bw0, bw1;
            asm volatile("ldmatrix.sync.aligned.m8n8.x2.trans.shared.b16 {%0,%1}, [%2];"
                : "=r"(bw0), "=r"(bw1) : "r"(addr_w));
            #pragma unroll
            for (int mt = 0; mt < 2; mt++) {
                asm volatile(
                    "mma.sync.aligned.m16n8k16.row.col.f32.f16.f16.f32 "
                    "{%0,%1,%2,%3}, {%4,%5,%6,%7}, {%8,%9}, {%0,%1,%2,%3};"
                    : "+f"(acc[mt][nt][0]), "+f"(acc[mt][nt][1]),
                      "+f"(acc[mt][nt][2]), "+f"(acc[mt][nt][3])
                    : "r"(a[mt][0]), "r"(a[mt][1]), "r"(a[mt][2]), "r"(a[mt][3]),
                      "r"(bw0), "r"(bw1));
            }
        }
    }

    int gid = lane >> 2, tig = lane & 3;
    #pragma unroll
    for (int mt = 0; mt < 2; mt++) {
        #pragma unroll
        for (int nt = 0; nt < 4; nt++) {
            int cbase = warp_n * 32 + nt * 8 + 2 * tig;
            float bx = bg[cbase], by = bg[cbase + 1];
            int r0 = block_m + warp_m * 32 + mt * 16 + gid;
            if (r0 < n) {
                float2 o;
                o.x = tanh_fast(acc[mt][nt][0] + bx);
                o.y = tanh_fast(acc[mt][nt][1] + by);
                *(float2*)&out[(size_t)r0 * OUTC + cbase] = o;
            }
            int r1 = r0 + 8;
            if (r1 < n) {
                float2 o;
                o.x = tanh_fast(acc[mt][nt][2] + bx);
                o.y = tanh_fast(acc[mt][nt][3] + by);
                *(float2*)&out[(size_t)r1 * OUTC + cbase] = o;
            }
        }
    }
}

// ---------------- launch ----------------

extern "C" void kernel_launch(void* const* d_in, const int* in_sizes, int n_in,
                              void* d_out, int out_size) {
    const int*   row  = (const int*)d_in[0];
    const int*   col  = (const int*)d_in[1];
    const float* feat = (const float*)d_in[2];
    const float* W    = (const float*)d_in[3];
    const float* b    = (const float*)d_in[4];
    float* out = (float*)d_out;

    int E = in_sizes[0];
    int N = in_sizes[2] / D;
    int nb = (N + SCAN_B - 1) / SCAN_B;
    int total4 = N * D / 4;
    int prep_n = (total4 > E) ? total4 : E;

    cudaFuncSetAttribute(mlp_gemm_kernel,
                         cudaFuncAttributeMaxDynamicSharedMemorySize, GEMM_SMEM_BYTES);

    prep_kernel<<<(prep_n + 255) / 256, 256>>>(feat, row, W, total4, E);
    scan_lookback_kernel<<<nb, SCAN_B>>>(N, nb);
    scatter_kernel<<<(E + 255) / 256, 256>>>(row, col, E);
    aggregate_kernel<<<(N * 16 + 255) / 256, 256>>>(N);
    mlp_gemm_kernel<<<(N + GBM - 1) / GBM, 256, GEMM_SMEM_BYTES>>>(b, out, N);
}